// round 1
// baseline (speedup 1.0000x reference)
#include <cuda_runtime.h>
#include <math.h>

#define O_   16
#define C_   64
#define NN   576
#define LL   1024
#define B_   8
#define EPSN 1e-4f

// Scratch (no cudaMalloc allowed): X powers and inverse covariance.
__device__ float g_X[O_ * NN * 8];   // [o][n][p-1], p=1..8 : [w1,w2,w1^2,w2^2,w1^3,w2^3,w1^4,w2^4]
__device__ float g_A[O_ * 81];       // [o][p][q] = inv(X^T X), 9x9 incl. ones column (p=0)

// ---------------------------------------------------------------------------
// Kernel 1: build polynomial feature matrix X from weights (16,64,3,3,2).
// n = c*9 + ki*3 + kj  matches torch unfold channel-major ordering.
// ---------------------------------------------------------------------------
__global__ void build_X(const float* __restrict__ w) {
    int o = blockIdx.x;
    for (int n = threadIdx.x; n < NN; n += blockDim.x) {
        float w1 = w[(o * NN + n) * 2 + 0];
        float w2 = w[(o * NN + n) * 2 + 1];
        float* dst = &g_X[(o * NN + n) * 8];
        float a1 = w1, a2 = w2;
        dst[0] = a1; dst[1] = a2;
        a1 *= w1; a2 *= w2; dst[2] = a1; dst[3] = a2;
        a1 *= w1; a2 *= w2; dst[4] = a1; dst[5] = a2;
        a1 *= w1; a2 *= w2; dst[6] = a1; dst[7] = a2;
    }
}

// ---------------------------------------------------------------------------
// Kernel 2: per-o: Xcov = X^T X (fp64 accumulate of fp32 products), then
// Gauss-Jordan inverse in fp64 shared memory. One block per o.
// ---------------------------------------------------------------------------
__global__ void build_A_kernel() {
    __shared__ double Cm[9][19];   // augmented [cov | I]
    __shared__ double f[9];
    int o = blockIdx.x;
    int tid = threadIdx.x;
    const float* Xo = g_X + o * NN * 8;

    for (int e = tid; e < 81; e += blockDim.x) {
        int p = e / 9, q = e % 9;
        double s = 0.0;
        for (int n = 0; n < NN; n++) {
            float xp = (p == 0) ? 1.0f : Xo[n * 8 + (p - 1)];
            float xq = (q == 0) ? 1.0f : Xo[n * 8 + (q - 1)];
            s += (double)xp * (double)xq;
        }
        Cm[p][q] = s;
    }
    for (int e = tid; e < 81; e += blockDim.x) {
        int p = e / 9, q = e % 9;
        Cm[p][9 + q] = (p == q) ? 1.0 : 0.0;
    }
    __syncthreads();

    for (int k = 0; k < 9; k++) {
        if (tid < 9) f[tid] = Cm[tid][k];
        __syncthreads();
        if (tid < 18) Cm[k][tid] = Cm[k][tid] / f[k];
        __syncthreads();
        for (int e = tid; e < 162; e += blockDim.x) {
            int ii = e / 18, jj = e % 18;
            if (ii != k) Cm[ii][jj] -= f[ii] * Cm[k][jj];
        }
        __syncthreads();
    }
    for (int e = tid; e < 81; e += blockDim.x)
        g_A[o * 81 + e] = (float)Cm[e / 9][9 + (e % 9)];
}

// ---------------------------------------------------------------------------
// Kernel 3: main fused kernel.
// Block = (b, image row i). Stage u[576][32] in smem, compute z0/S2, then
// the 128x576 "GEMM" slice (16 o x 8 poly rows) x 32 locations, then the
// 9x9 quadratic-form epilogue and exp(-err).
// Threads: t -> o = t>>3 (16), g = t&7 (8), each handles 4 locations.
// ---------------------------------------------------------------------------
__global__ void __launch_bounds__(128) srn_main(
    const float* __restrict__ y2,
    const float* __restrict__ noise,
    float* __restrict__ out)
{
    extern __shared__ float sm[];
    float* su  = sm;               // [576][32]
    float* red = sm + NN * 32;     // [4][32][2]
    float* z0s = red + 256;        // [32]
    float* s2s = z0s + 32;         // [32]

    int b = blockIdx.x >> 5;
    int i = blockIdx.x & 31;
    int t = threadIdx.x;

    // ---- build u = unfold(y2) + eps*noise for this image row ----
    const float* y2b = y2 + b * (C_ * 32 * 32);
    const float* nzb = noise + (size_t)b * (NN * LL) + i * 32;
    for (int idx = t; idx < NN * 32; idx += 128) {
        int n = idx >> 5;
        int j = idx & 31;
        int c  = n / 9;
        int kk = n - c * 9;
        int ki = kk / 3, kj = kk - ki * 3;
        int r  = i + ki - 1;
        int cc = j + kj - 1;
        float v = 0.0f;
        if ((unsigned)r < 32u && (unsigned)cc < 32u)
            v = y2b[(c * 32 + r) * 32 + cc];
        v += EPSN * nzb[n * LL + j];
        su[idx] = v;
    }
    __syncthreads();

    // ---- z0 and S2 per location (4-way split reduction over n) ----
    {
        int j = t & 31, part = t >> 5;
        float s1 = 0.0f, s2 = 0.0f;
        int n0 = part * 144;
        for (int n = n0; n < n0 + 144; n++) {
            float v = su[n * 32 + j];
            s1 += v;
            s2 += v * v;
        }
        red[(part * 32 + j) * 2 + 0] = s1;
        red[(part * 32 + j) * 2 + 1] = s2;
    }
    __syncthreads();
    if (t < 32) {
        float s1 = 0.0f, s2 = 0.0f;
        #pragma unroll
        for (int p = 0; p < 4; p++) {
            s1 += red[(p * 32 + t) * 2 + 0];
            s2 += red[(p * 32 + t) * 2 + 1];
        }
        z0s[t] = s1;
        s2s[t] = s2;
    }
    __syncthreads();

    // ---- main accumulation: w[p][jj] = sum_n X[o,n,p] * u[n, 4g+jj] ----
    int o = t >> 3;
    int g = t & 7;

    float acc[8][4];
    #pragma unroll
    for (int p = 0; p < 8; p++)
        #pragma unroll
        for (int jj = 0; jj < 4; jj++)
            acc[p][jj] = 0.0f;

    const float4* X4  = (const float4*)(g_X + (size_t)o * NN * 8);
    const float4* su4 = (const float4*)su;

    #pragma unroll 2
    for (int n = 0; n < NN; n++) {
        float4 uu = su4[n * 8 + g];
        float4 xa = X4[2 * n];
        float4 xb = X4[2 * n + 1];
        float xs[8] = {xa.x, xa.y, xa.z, xa.w, xb.x, xb.y, xb.z, xb.w};
        float us[4] = {uu.x, uu.y, uu.z, uu.w};
        #pragma unroll
        for (int p = 0; p < 8; p++)
            #pragma unroll
            for (int jj = 0; jj < 4; jj++)
                acc[p][jj] = fmaf(xs[p], us[jj], acc[p][jj]);
    }

    // ---- epilogue: wAw, err, exp(-err) ----
    float w0v[4], wAw[4];
    #pragma unroll
    for (int jj = 0; jj < 4; jj++) {
        w0v[jj] = z0s[g * 4 + jj];
        wAw[jj] = 0.0f;
    }
    const float* A = g_A + o * 81;
    #pragma unroll
    for (int p = 0; p < 9; p++) {
        float tp[4] = {0.0f, 0.0f, 0.0f, 0.0f};
        #pragma unroll
        for (int q = 0; q < 9; q++) {
            float a = __ldg(&A[p * 9 + q]);
            #pragma unroll
            for (int jj = 0; jj < 4; jj++) {
                float v = (q == 0) ? w0v[jj] : acc[q - 1][jj];
                tp[jj] = fmaf(a, v, tp[jj]);
            }
        }
        #pragma unroll
        for (int jj = 0; jj < 4; jj++) {
            float v = (p == 0) ? w0v[jj] : acc[p - 1][jj];
            wAw[jj] = fmaf(tp[jj], v, wAw[jj]);
        }
    }

    float4 res;
    #pragma unroll
    for (int jj = 0; jj < 4; jj++) {
        int j = g * 4 + jj;
        float S2 = s2s[j];
        float z0 = w0v[jj];
        float denom = S2 - z0 * z0 * (1.0f / 576.0f);
        float err = (S2 - wAw[jj]) * (575.0f / 576.0f) / denom;
        ((float*)&res)[jj] = expf(-err);
    }
    *(float4*)(out + ((size_t)(b * 16 + o) * 1024 + i * 32 + g * 4)) = res;
}

// ---------------------------------------------------------------------------
extern "C" void kernel_launch(void* const* d_in, const int* in_sizes, int n_in,
                              void* d_out, int out_size) {
    const float* y2 = nullptr;
    const float* w  = nullptr;
    const float* nz = nullptr;
    for (int k = 0; k < n_in; k++) {
        if      (in_sizes[k] == 524288)  y2 = (const float*)d_in[k];
        else if (in_sizes[k] == 18432)   w  = (const float*)d_in[k];
        else if (in_sizes[k] == 4718592) nz = (const float*)d_in[k];
    }
    // positional fallback
    if (!y2 || !w || !nz) {
        y2 = (const float*)d_in[0];
        w  = (const float*)d_in[1];
        nz = (const float*)d_in[2];
    }

    build_X<<<O_, 192>>>(w);
    build_A_kernel<<<O_, 192>>>();

    const int smem_bytes = (NN * 32 + 256 + 32 + 32) * (int)sizeof(float); // 75008
    cudaFuncSetAttribute(srn_main, cudaFuncAttributeMaxDynamicSharedMemorySize, smem_bytes);
    srn_main<<<B_ * 32, 128, smem_bytes>>>(y2, nz, (float*)d_out);
}

// round 2
// speedup vs baseline: 2.2084x; 2.2084x over previous
#include <cuda_runtime.h>
#include <math.h>

#define O_   16
#define C_   64
#define NN   576
#define LL   1024
#define B_   8
#define CH   64          // K-chunk size
#define NCH  9           // 576 / 64
#define EPSN 1e-4f
#define XPAD (CH*8 + 4)  // 516 floats per o; +4 pad decorrelates banks across o

// Scratch (no cudaMalloc allowed)
__device__ float g_X[O_ * NN * 8];   // [o][n][p-1]: [w1,w2,w1^2,w2^2,w1^3,w2^3,w1^4,w2^4]
__device__ float g_A[O_ * 81];       // [o][9][9] = inv(X^T X) incl. ones column

// ---------------------------------------------------------------------------
// Build X powers AND the 9x9 inverse covariance in one kernel (1 block per o).
// ---------------------------------------------------------------------------
__global__ void build_XA(const float* __restrict__ w) {
    __shared__ float  sX[NN * 8];
    __shared__ double Cm[9][19];   // augmented [cov | I]
    __shared__ double f[9];
    int o = blockIdx.x, tid = threadIdx.x;

    for (int n = tid; n < NN; n += blockDim.x) {
        float w1 = w[(o * NN + n) * 2 + 0];
        float w2 = w[(o * NN + n) * 2 + 1];
        float* gd = &g_X[(o * NN + n) * 8];
        float* sd = &sX[n * 8];
        float a1 = w1, a2 = w2;
        #pragma unroll
        for (int d = 0; d < 4; d++) {
            gd[2*d] = a1; gd[2*d+1] = a2;
            sd[2*d] = a1; sd[2*d+1] = a2;
            a1 *= w1; a2 *= w2;
        }
    }
    __syncthreads();

    for (int e = tid; e < 81; e += blockDim.x) {
        int p = e / 9, q = e % 9;
        double s = 0.0;
        for (int n = 0; n < NN; n++) {
            float xp = p ? sX[n * 8 + p - 1] : 1.0f;
            float xq = q ? sX[n * 8 + q - 1] : 1.0f;
            s += (double)xp * (double)xq;
        }
        Cm[p][q] = s;
    }
    for (int e = tid; e < 81; e += blockDim.x) {
        int p = e / 9, q = e % 9;
        Cm[p][9 + q] = (p == q) ? 1.0 : 0.0;
    }
    __syncthreads();

    for (int k = 0; k < 9; k++) {
        if (tid < 9) f[tid] = Cm[tid][k];
        __syncthreads();
        if (tid < 18) Cm[k][tid] = Cm[k][tid] / f[k];
        __syncthreads();
        for (int e = tid; e < 162; e += blockDim.x) {
            int ii = e / 18, jj = e % 18;
            if (ii != k) Cm[ii][jj] -= f[ii] * Cm[k][jj];
        }
        __syncthreads();
    }
    for (int e = tid; e < 81; e += blockDim.x)
        g_A[o * 81 + e] = (float)Cm[e / 9][9 + (e % 9)];
}

// ---------------------------------------------------------------------------
// f32x2 packed-math helpers (FFMA2 path — ptxas never auto-fuses from C++)
// ---------------------------------------------------------------------------
__device__ __forceinline__ unsigned long long pk2(float a, float b) {
    unsigned long long r;
    asm("mov.b64 %0, {%1, %2};"
        : "=l"(r) : "r"(__float_as_uint(a)), "r"(__float_as_uint(b)));
    return r;
}
#define FMA2(acc_, x_, u_) \
    asm("fma.rn.f32x2 %0, %1, %2, %0;" : "+l"(acc_) : "l"(x_), "l"(u_))

// ---------------------------------------------------------------------------
// Main fused kernel. Block = (b, image row i): 32 locations x 16 o.
// Threads 256: o = t>>4, g = t&15 -> 2 locations (j0=2g, 2g+1), 8 poly rows
// packed pairwise over p into f32x2 accumulators (acc[4*jj+pp]).
// K-chunked: stage X chunk (33KB) + u chunk (8KB) in smem each iteration.
// ---------------------------------------------------------------------------
__global__ void __launch_bounds__(256, 2) srn_main(
    const float* __restrict__ y2,
    const float* __restrict__ noise,
    float* __restrict__ out)
{
    __shared__ float us[CH * 32];        // u chunk [64 n][32 j]
    __shared__ float xs[O_ * XPAD];      // X chunk [16 o][64 n * 8 p (+pad)]
    __shared__ float red1[256], red2[256];
    __shared__ float z0s[32], s2s[32];

    int b = blockIdx.x >> 5;
    int i = blockIdx.x & 31;
    int t = threadIdx.x;
    int o = t >> 4;
    int g = t & 15;
    int j0 = g * 2;

    unsigned long long acc[8];
    #pragma unroll
    for (int p = 0; p < 8; p++) acc[p] = 0ULL;
    float s1 = 0.0f, s2 = 0.0f;

    const float* y2b = y2 + b * (C_ * 32 * 32);
    const float* nzb = noise + (size_t)b * (NN * LL) + (size_t)i * 32;

    for (int c = 0; c < NCH; c++) {
        __syncthreads();   // previous chunk's compute done before overwrite

        // ---- stage X chunk: 2048 float4, fully coalesced ----
        #pragma unroll
        for (int k = t; k < 2048; k += 256) {
            int o2 = k >> 7;        // 128 float4 per o per chunk
            int r  = k & 127;
            ((float4*)xs)[o2 * (XPAD / 4) + r] =
                ((const float4*)g_X)[o2 * (NN * 2) + c * 128 + r];
        }

        // ---- stage u chunk = unfold(y2) + eps*noise; accumulate z0/S2 ----
        #pragma unroll
        for (int k = t; k < CH * 32; k += 256) {
            int nl = k >> 5;
            int j  = k & 31;        // == t&31 for all iterations (stride 256)
            int n  = c * CH + nl;
            int ch = n / 9;
            int kk = n - ch * 9;
            int ki = kk / 3, kj = kk - ki * 3;
            int r  = i + ki - 1;
            int cc = j + kj - 1;
            float v = 0.0f;
            if ((unsigned)r < 32u && (unsigned)cc < 32u)
                v = y2b[(ch * 32 + r) * 32 + cc];
            v += EPSN * nzb[(size_t)n * LL + j];
            us[k] = v;
            s1 += v;
            s2 += v * v;
        }
        __syncthreads();

        // ---- compute: acc[4*jj+pp] += X[p-pair] * u[j0+jj] ----
        const float* xo = xs + o * XPAD;
        #pragma unroll 4
        for (int n = 0; n < CH; n++) {
            float2 uu = *(const float2*)(us + n * 32 + j0);
            unsigned long long ua = pk2(uu.x, uu.x);
            unsigned long long ub = pk2(uu.y, uu.y);
            float4 xa = *(const float4*)(xo + n * 8);
            float4 xb = *(const float4*)(xo + n * 8 + 4);
            unsigned long long x01 = pk2(xa.x, xa.y);
            unsigned long long x23 = pk2(xa.z, xa.w);
            unsigned long long x45 = pk2(xb.x, xb.y);
            unsigned long long x67 = pk2(xb.z, xb.w);
            FMA2(acc[0], x01, ua); FMA2(acc[1], x23, ua);
            FMA2(acc[2], x45, ua); FMA2(acc[3], x67, ua);
            FMA2(acc[4], x01, ub); FMA2(acc[5], x23, ub);
            FMA2(acc[6], x45, ub); FMA2(acc[7], x67, ub);
        }
    }

    // ---- z0 / S2 reduction (thread t always built column t&31) ----
    red1[t] = s1;
    red2[t] = s2;
    __syncthreads();
    if (t < 32) {
        float a = 0.0f, bb = 0.0f;
        #pragma unroll
        for (int w8 = 0; w8 < 8; w8++) {
            a  += red1[w8 * 32 + t];
            bb += red2[w8 * 32 + t];
        }
        z0s[t] = a;
        s2s[t] = bb;
    }
    __syncthreads();

    // ---- unpack accumulators: wv[jj][p] ----
    float wv[2][8];
    #pragma unroll
    for (int jj = 0; jj < 2; jj++)
        #pragma unroll
        for (int pp = 0; pp < 4; pp++) {
            unsigned long long a = acc[4 * jj + pp];
            wv[jj][2 * pp]     = __uint_as_float((unsigned)a);
            wv[jj][2 * pp + 1] = __uint_as_float((unsigned)(a >> 32));
        }

    // ---- epilogue: wAw, err, exp(-err) ----
    float w0v[2], wAw[2];
    #pragma unroll
    for (int jj = 0; jj < 2; jj++) {
        w0v[jj] = z0s[j0 + jj];
        wAw[jj] = 0.0f;
    }
    const float* A = g_A + o * 81;
    #pragma unroll
    for (int p = 0; p < 9; p++) {
        float tp[2] = {0.0f, 0.0f};
        #pragma unroll
        for (int q = 0; q < 9; q++) {
            float a = __ldg(&A[p * 9 + q]);
            #pragma unroll
            for (int jj = 0; jj < 2; jj++) {
                float v = (q == 0) ? w0v[jj] : wv[jj][q - 1];
                tp[jj] = fmaf(a, v, tp[jj]);
            }
        }
        #pragma unroll
        for (int jj = 0; jj < 2; jj++) {
            float v = (p == 0) ? w0v[jj] : wv[jj][p - 1];
            wAw[jj] = fmaf(tp[jj], v, wAw[jj]);
        }
    }

    float2 res;
    #pragma unroll
    for (int jj = 0; jj < 2; jj++) {
        float S2 = s2s[j0 + jj];
        float z0 = w0v[jj];
        float denom = S2 - z0 * z0 * (1.0f / 576.0f);
        float err = (S2 - wAw[jj]) * (575.0f / 576.0f) / denom;
        ((float*)&res)[jj] = expf(-err);
    }
    *(float2*)(out + ((size_t)(b * 16 + o) * 1024 + i * 32 + j0)) = res;
}

// ---------------------------------------------------------------------------
extern "C" void kernel_launch(void* const* d_in, const int* in_sizes, int n_in,
                              void* d_out, int out_size) {
    const float* y2 = nullptr;
    const float* w  = nullptr;
    const float* nz = nullptr;
    for (int k = 0; k < n_in; k++) {
        if      (in_sizes[k] == 524288)  y2 = (const float*)d_in[k];
        else if (in_sizes[k] == 18432)   w  = (const float*)d_in[k];
        else if (in_sizes[k] == 4718592) nz = (const float*)d_in[k];
    }
    if (!y2 || !w || !nz) {
        y2 = (const float*)d_in[0];
        w  = (const float*)d_in[1];
        nz = (const float*)d_in[2];
    }

    build_XA<<<O_, 192>>>(w);
    srn_main<<<B_ * 32, 256>>>(y2, nz, (float*)d_out);
}

// round 4
// speedup vs baseline: 2.5720x; 1.1646x over previous
#include <cuda_runtime.h>
#include <math.h>

#define O_   16
#define C_   64
#define NN   576
#define LL   1024
#define B_   8
#define CH   64          // K-chunk size
#define NCH  9           // 576 / 64
#define EPSN 1e-4f

// Scratch (no cudaMalloc allowed)
__device__ float g_A[O_ * 81];       // [o][9][9] = inv(X^T X) incl. ones column (p=0)

// ---------------------------------------------------------------------------
// packed f32x2 helpers
// ---------------------------------------------------------------------------
__device__ __forceinline__ unsigned long long pk2(float a, float b) {
    unsigned long long r;
    asm("mov.b64 %0, {%1, %2};"
        : "=l"(r) : "r"(__float_as_uint(a)), "r"(__float_as_uint(b)));
    return r;
}
#define FMA2(acc_, x_, u_) \
    asm("fma.rn.f32x2 %0, %1, %2, %0;" : "+l"(acc_) : "l"(x_), "l"(u_))
#define MUL2(d_, a_, b_) \
    asm("mul.rn.f32x2 %0, %1, %2;" : "=l"(d_) : "l"(a_), "l"(b_))

// ---------------------------------------------------------------------------
// Build inverse covariance A[o] = inv(X^T X) directly from weights.
// One block per o. Powers precomputed in smem; fp64 cov with 8-way n-split
// (breaks the 576-long dependent fp64 chain that cost ~15us in R2).
// ---------------------------------------------------------------------------
__global__ void __launch_bounds__(672) build_A(const float* __restrict__ w) {
    __shared__ float  sXp[NN * 9];     // [n][p], p=0..8 (p=0 -> 1.0)
    __shared__ double sPart[81 * 8];
    __shared__ double Cm[9][19];
    __shared__ double f[9];
    int o = blockIdx.x, tid = threadIdx.x;

    for (int n = tid; n < NN; n += blockDim.x) {
        float w1 = w[(o * NN + n) * 2 + 0];
        float w2 = w[(o * NN + n) * 2 + 1];
        float* d = &sXp[n * 9];
        d[0] = 1.0f;
        float a1 = w1, a2 = w2;
        #pragma unroll
        for (int dg = 0; dg < 4; dg++) {
            d[1 + 2 * dg] = a1;
            d[2 + 2 * dg] = a2;
            a1 *= w1; a2 *= w2;
        }
    }
    __syncthreads();

    if (tid < 648) {
        int pair = tid >> 3;           // 0..80
        int sl   = tid & 7;            // 0..7
        int p = pair / 9, q = pair % 9;
        double s0 = 0.0, s1 = 0.0;
        int n0 = sl * 72;
        #pragma unroll 4
        for (int n = n0; n < n0 + 72; n += 2) {
            s0 += (double)sXp[n * 9 + p]       * (double)sXp[n * 9 + q];
            s1 += (double)sXp[(n + 1) * 9 + p] * (double)sXp[(n + 1) * 9 + q];
        }
        sPart[pair * 8 + sl] = s0 + s1;
    }
    __syncthreads();

    if (tid < 81) {
        double s = 0.0;
        #pragma unroll
        for (int sl = 0; sl < 8; sl++) s += sPart[tid * 8 + sl];
        Cm[tid / 9][tid % 9] = s;
    }
    for (int e = tid; e < 81; e += blockDim.x)
        Cm[e / 9][9 + e % 9] = (e / 9 == e % 9) ? 1.0 : 0.0;
    __syncthreads();

    for (int k = 0; k < 9; k++) {
        if (tid < 9) f[tid] = Cm[tid][k];
        __syncthreads();
        if (tid < 18) Cm[k][tid] = Cm[k][tid] / f[k];
        __syncthreads();
        for (int e = tid; e < 162; e += blockDim.x) {
            int ii = e / 18, jj = e % 18;
            if (ii != k) Cm[ii][jj] -= f[ii] * Cm[k][jj];
        }
        __syncthreads();
    }
    for (int e = tid; e < 81; e += blockDim.x)
        g_A[o * 81 + e] = (float)Cm[e / 9][9 + e % 9];
}

// ---------------------------------------------------------------------------
// Main fused kernel. Block = (b, image row i): 32 locations x 16 o.
// 256 threads: h = t>>7 (n-half), o = (t>>3)&15, g = t&7 -> 4 locations.
// Per n: load packed (w1,w2) from smem (8B), compute powers via 3 MUL2,
// load u float4 (16B), 16 FMA2. K-chunked staging of u (unfold+noise) and
// raw weights. Final cross-half acc reduction in smem, then 9x9 quadratic
// form epilogue and exp(-err).
// ---------------------------------------------------------------------------
__global__ void __launch_bounds__(256, 2) srn_main(
    const float* __restrict__ y2,
    const float* __restrict__ wgt,
    const float* __restrict__ noise,
    float* __restrict__ out)
{
    __shared__ float  us[CH * 32];         // u chunk [64 n][32 j]     8KB
    __shared__ float2 xw2[CH * 17];        // [nl][o] (+pad)           8.5KB
    __shared__ float  red[4096];           // reductions               16KB
    __shared__ float  z0s[32], s2s[32];

    int b = blockIdx.x >> 5;
    int i = blockIdx.x & 31;
    int t = threadIdx.x;
    int h = t >> 7;            // n-half
    int r = t & 127;
    int o = r >> 3;
    int g = r & 7;
    int j0 = g * 4;

    unsigned long long acc[16];            // [loc 4][p-pair 4]
    #pragma unroll
    for (int k = 0; k < 16; k++) acc[k] = 0ULL;
    float s1 = 0.0f, s2 = 0.0f;

    const float* y2b = y2 + b * (C_ * 32 * 32);
    const float* nzb = noise + (size_t)b * (NN * LL) + (size_t)i * 32;

    for (int c = 0; c < NCH; c++) {
        __syncthreads();

        // ---- stage weights chunk: 1024 float2, coalesced per 64-thread group
        #pragma unroll
        for (int k = t; k < CH * O_; k += 256) {
            int oo = k >> 6;          // 0..15
            int nl = k & 63;
            xw2[nl * 17 + oo] =
                ((const float2*)wgt)[oo * NN + c * CH + nl];
        }

        // ---- stage u chunk = unfold(y2) + eps*noise; accumulate z0/S2 ----
        #pragma unroll
        for (int k = t; k < CH * 32; k += 256) {
            int nl = k >> 5;
            int j  = k & 31;          // == t&31 every iteration
            int n  = c * CH + nl;
            int ch = n / 9;
            int kk = n - ch * 9;
            int ki = kk / 3, kj = kk - ki * 3;
            int rr = i + ki - 1;
            int cc = j + kj - 1;
            float v = 0.0f;
            if ((unsigned)rr < 32u && (unsigned)cc < 32u)
                v = y2b[(ch * 32 + rr) * 32 + cc];
            v += EPSN * nzb[(size_t)n * LL + j];
            us[k] = v;
            s1 += v;
            s2 += v * v;
        }
        __syncthreads();

        // ---- compute over this thread's n-half ----
        int nbase = h * 32;
        #pragma unroll 4
        for (int nl = 0; nl < 32; nl++) {
            int n2 = nbase + nl;
            float4 uu = *(const float4*)(us + n2 * 32 + j0);
            float2 xv = xw2[n2 * 17 + o];
            unsigned long long m1 = pk2(xv.x, xv.y);
            unsigned long long m2, m3, m4;
            MUL2(m2, m1, m1);
            MUL2(m3, m2, m1);
            MUL2(m4, m2, m2);
            unsigned long long ua = pk2(uu.x, uu.x);
            unsigned long long ub = pk2(uu.y, uu.y);
            unsigned long long uc = pk2(uu.z, uu.z);
            unsigned long long ud = pk2(uu.w, uu.w);
            FMA2(acc[0],  m1, ua); FMA2(acc[1],  m2, ua);
            FMA2(acc[2],  m3, ua); FMA2(acc[3],  m4, ua);
            FMA2(acc[4],  m1, ub); FMA2(acc[5],  m2, ub);
            FMA2(acc[6],  m3, ub); FMA2(acc[7],  m4, ub);
            FMA2(acc[8],  m1, uc); FMA2(acc[9],  m2, uc);
            FMA2(acc[10], m3, uc); FMA2(acc[11], m4, uc);
            FMA2(acc[12], m1, ud); FMA2(acc[13], m2, ud);
            FMA2(acc[14], m3, ud); FMA2(acc[15], m4, ud);
        }
    }

    // ---- z0 / S2 reduction (thread t built column t&31) ----
    red[t] = s1;
    red[256 + t] = s2;
    __syncthreads();
    if (t < 32) {
        float a = 0.0f, bb = 0.0f;
        #pragma unroll
        for (int w8 = 0; w8 < 8; w8++) {
            a  += red[w8 * 32 + t];
            bb += red[256 + w8 * 32 + t];
        }
        z0s[t] = a;
        s2s[t] = bb;
    }
    __syncthreads();

    // ---- cross-half acc reduction ----
    if (h == 1) {
        #pragma unroll
        for (int k = 0; k < 16; k++) {
            red[r * 32 + 2 * k]     = __uint_as_float((unsigned)acc[k]);
            red[r * 32 + 2 * k + 1] = __uint_as_float((unsigned)(acc[k] >> 32));
        }
    }
    __syncthreads();

    if (h == 0) {
        // wv[loc][p]: acc layout acc[loc*4 + pp] packs (p=2pp, p=2pp+1)
        float wv[4][8];
        #pragma unroll
        for (int loc = 0; loc < 4; loc++)
            #pragma unroll
            for (int pp = 0; pp < 4; pp++) {
                unsigned long long a = acc[loc * 4 + pp];
                int k = loc * 4 + pp;
                wv[loc][2 * pp]     = __uint_as_float((unsigned)a)         + red[r * 32 + 2 * k];
                wv[loc][2 * pp + 1] = __uint_as_float((unsigned)(a >> 32)) + red[r * 32 + 2 * k + 1];
            }

        float w0v[4], wAw[4];
        #pragma unroll
        for (int loc = 0; loc < 4; loc++) {
            w0v[loc] = z0s[j0 + loc];
            wAw[loc] = 0.0f;
        }
        const float* A = g_A + o * 81;
        #pragma unroll
        for (int p = 0; p < 9; p++) {
            float tp[4] = {0.0f, 0.0f, 0.0f, 0.0f};
            #pragma unroll
            for (int q = 0; q < 9; q++) {
                float a = __ldg(&A[p * 9 + q]);
                #pragma unroll
                for (int loc = 0; loc < 4; loc++) {
                    float v = (q == 0) ? w0v[loc] : wv[loc][q - 1];
                    tp[loc] = fmaf(a, v, tp[loc]);
                }
            }
            #pragma unroll
            for (int loc = 0; loc < 4; loc++) {
                float v = (p == 0) ? w0v[loc] : wv[loc][p - 1];
                wAw[loc] = fmaf(tp[loc], v, wAw[loc]);
            }
        }

        float4 res;
        #pragma unroll
        for (int loc = 0; loc < 4; loc++) {
            float S2 = s2s[j0 + loc];
            float z0 = w0v[loc];
            float denom = S2 - z0 * z0 * (1.0f / 576.0f);
            float err = (S2 - wAw[loc]) * (575.0f / 576.0f) / denom;
            ((float*)&res)[loc] = expf(-err);
        }
        *(float4*)(out + ((size_t)(b * 16 + o) * 1024 + i * 32 + j0)) = res;
    }
}

// ---------------------------------------------------------------------------
extern "C" void kernel_launch(void* const* d_in, const int* in_sizes, int n_in,
                              void* d_out, int out_size) {
    const float* y2 = nullptr;
    const float* w  = nullptr;
    const float* nz = nullptr;
    for (int k = 0; k < n_in; k++) {
        if      (in_sizes[k] == 524288)  y2 = (const float*)d_in[k];
        else if (in_sizes[k] == 18432)   w  = (const float*)d_in[k];
        else if (in_sizes[k] == 4718592) nz = (const float*)d_in[k];
    }
    if (!y2 || !w || !nz) {
        y2 = (const float*)d_in[0];
        w  = (const float*)d_in[1];
        nz = (const float*)d_in[2];
    }

    build_A<<<O_, 672>>>(w);
    srn_main<<<B_ * 32, 256>>>(y2, w, nz, (float*)d_out);
}

// round 6
// speedup vs baseline: 2.6843x; 1.0437x over previous
#include <cuda_runtime.h>
#include <math.h>

#define O_   16
#define C_   64
#define NN   576
#define LL   1024
#define B_   8
#define CH   64          // K-chunk size
#define NCH  9           // 576 / 64
#define EPSN 1e-4f
#define WPITCH 68        // float2 pitch per o row in wbuf (64 + 4 pad)

// Scratch (no cudaMalloc allowed)
__device__ float g_A[O_ * 81];       // [o][9][9] = inv(X^T X) incl. ones column (p=0)

// ---------------------------------------------------------------------------
// packed f32x2 helpers
// ---------------------------------------------------------------------------
__device__ __forceinline__ unsigned long long pk2(float a, float b) {
    unsigned long long r;
    asm("mov.b64 %0, {%1, %2};"
        : "=l"(r) : "r"(__float_as_uint(a)), "r"(__float_as_uint(b)));
    return r;
}
#define FMA2(acc_, x_, u_) \
    asm("fma.rn.f32x2 %0, %1, %2, %0;" : "+l"(acc_) : "l"(x_), "l"(u_))
#define MUL2(d_, a_, b_) \
    asm("mul.rn.f32x2 %0, %1, %2;" : "=l"(d_) : "l"(a_), "l"(b_))

// cp.async helpers
__device__ __forceinline__ void cp16(unsigned dst, const void* src) {
    asm volatile("cp.async.cg.shared.global [%0], [%1], 16;"
                 :: "r"(dst), "l"(src));
}
__device__ __forceinline__ void cp4z(unsigned dst, const void* src, int pred) {
    asm volatile("cp.async.ca.shared.global [%0], [%1], 4, %2;"
                 :: "r"(dst), "l"(src), "r"(pred ? 4 : 0));
}
#define CP_COMMIT() asm volatile("cp.async.commit_group;")
#define CP_WAIT0()  asm volatile("cp.async.wait_group 0;")

// ---------------------------------------------------------------------------
// Build inverse covariance A[o] = inv(X^T X). One block per o.
// Powers in smem; fp64 cov with 8-way n-split (short dependency chains).
// ---------------------------------------------------------------------------
__global__ void __launch_bounds__(672) build_A(const float* __restrict__ w) {
    __shared__ float  sXp[NN * 9];     // [n][p], p=0..8 (p=0 -> 1.0)
    __shared__ double sPart[81 * 8];
    __shared__ double Cm[9][19];
    __shared__ double f[9];
    int o = blockIdx.x, tid = threadIdx.x;

    for (int n = tid; n < NN; n += blockDim.x) {
        float w1 = w[(o * NN + n) * 2 + 0];
        float w2 = w[(o * NN + n) * 2 + 1];
        float* d = &sXp[n * 9];
        d[0] = 1.0f;
        float a1 = w1, a2 = w2;
        #pragma unroll
        for (int dg = 0; dg < 4; dg++) {
            d[1 + 2 * dg] = a1;
            d[2 + 2 * dg] = a2;
            a1 *= w1; a2 *= w2;
        }
    }
    __syncthreads();

    if (tid < 648) {
        int pair = tid >> 3;
        int sl   = tid & 7;
        int p = pair / 9, q = pair % 9;
        double s0 = 0.0, s1 = 0.0;
        int n0 = sl * 72;
        #pragma unroll 4
        for (int n = n0; n < n0 + 72; n += 2) {
            s0 += (double)sXp[n * 9 + p]       * (double)sXp[n * 9 + q];
            s1 += (double)sXp[(n + 1) * 9 + p] * (double)sXp[(n + 1) * 9 + q];
        }
        sPart[pair * 8 + sl] = s0 + s1;
    }
    __syncthreads();

    if (tid < 81) {
        double s = 0.0;
        #pragma unroll
        for (int sl = 0; sl < 8; sl++) s += sPart[tid * 8 + sl];
        Cm[tid / 9][tid % 9] = s;
    }
    for (int e = tid; e < 81; e += blockDim.x)
        Cm[e / 9][9 + e % 9] = (e / 9 == e % 9) ? 1.0 : 0.0;
    __syncthreads();

    for (int k = 0; k < 9; k++) {
        if (tid < 9) f[tid] = Cm[tid][k];
        __syncthreads();
        if (tid < 18) Cm[k][tid] = Cm[k][tid] / f[k];
        __syncthreads();
        for (int e = tid; e < 162; e += blockDim.x) {
            int ii = e / 18, jj = e % 18;
            if (ii != k) Cm[ii][jj] -= f[ii] * Cm[k][jj];
        }
        __syncthreads();
    }
    for (int e = tid; e < 81; e += blockDim.x)
        g_A[o * 81 + e] = (float)Cm[e / 9][9 + e % 9];
}

// ---------------------------------------------------------------------------
// Stage chunk cc into parity pb (cp.async only; caller commits).
// ---------------------------------------------------------------------------
__device__ __forceinline__ void stage_chunk(
    int cc, int pb, int t, int i,
    unsigned us_b, unsigned nb_b, unsigned wb_b,
    const float* __restrict__ y2b,
    const char*  __restrict__ nzb,
    const char*  __restrict__ wgb)
{
    // noise: 512 x 16B granules (row nl of chunk, 8 granules per row)
    #pragma unroll
    for (int g2 = 0; g2 < 2; g2++) {
        int gran = t + g2 * 256;
        int nl = gran >> 3;
        cp16(nb_b + pb * 8192 + gran * 16,
             nzb + ((size_t)(cc * CH + nl)) * (LL * 4) + (gran & 7) * 16);
    }
    // weights: 512 x 16B granules -> [o][64 float2 + pad] pitch WPITCH
    #pragma unroll
    for (int g2 = 0; g2 < 2; g2++) {
        int gran = t + g2 * 256;
        int oo = gran >> 5;
        int gi = gran & 31;
        cp16(wb_b + pb * 8704 + oo * (WPITCH * 8) + gi * 16,
             wgb + ((size_t)(oo * NN + cc * CH + gi * 2)) * 8);
    }
    // y2 unfold: 8 x 4B zfill cp.async per thread
    #pragma unroll
    for (int ii = 0; ii < 8; ii++) {
        int k = t + ii * 256;
        int n  = cc * CH + (k >> 5);
        int j  = k & 31;
        int ch = n / 9;
        int kk = n - ch * 9;
        int ki = kk / 3, kj = kk - ki * 3;
        int rr = i + ki - 1;
        int cl = j + kj - 1;
        int ok = ((unsigned)rr < 32u) & ((unsigned)cl < 32u);
        const float* srcp = ok ? (y2b + (ch * 32 + rr) * 32 + cl) : y2b;
        cp4z(us_b + pb * 8192 + k * 4, srcp, ok);
    }
}

// ---------------------------------------------------------------------------
// Main fused kernel with cp.async double-buffered staging.
// Block = (b, image row i): 32 locations x 16 o. 256 threads:
// h = t>>7 (n-half), o = (t>>3)&15, g = t&7 -> 4 locations.
// Dynamic smem layout (floats):
//   us   [2][2048]  @ 0      (u chunk: y2-part via cp.async zfill, then +=noise)
//   nbuf [2][2048]  @ 4096   (noise chunk, cp.async.cg)
//   wbuf [2][16*68] @ 8192   (weights as float2, [o][64+pad])
//   red  [4096]     @ 12544
//   z0s/s2s         @ 16640 / 16672
// ---------------------------------------------------------------------------
__global__ void __launch_bounds__(256, 2) srn_main(
    const float* __restrict__ y2,
    const float* __restrict__ wgt,
    const float* __restrict__ noise,
    float* __restrict__ out)
{
    extern __shared__ float sm[];
    float*  us   = sm;                   // 2 x 2048
    float*  nb   = sm + 4096;            // 2 x 2048
    float2* wb   = (float2*)(sm + 8192); // 2 x 1088 float2
    float*  red  = sm + 12544;           // 4096
    float*  z0s  = sm + 16640;
    float*  s2s  = sm + 16672;

    unsigned sbase = (unsigned)__cvta_generic_to_shared(sm);
    const unsigned us_b = sbase;
    const unsigned nb_b = sbase + 4096 * 4;
    const unsigned wb_b = sbase + 8192 * 4;

    int b = blockIdx.x >> 5;
    int i = blockIdx.x & 31;
    int t = threadIdx.x;
    int h = t >> 7;
    int r = t & 127;
    int o = r >> 3;
    int g = r & 7;
    int j0 = g * 4;

    unsigned long long acc[16];
    #pragma unroll
    for (int k = 0; k < 16; k++) acc[k] = 0ULL;
    float s1 = 0.0f, s2 = 0.0f;

    const float* y2b = y2 + b * (C_ * 32 * 32);
    const char*  nzb = (const char*)(noise + (size_t)b * (NN * LL) + (size_t)i * 32);
    const char*  wgb = (const char*)wgt;

    stage_chunk(0, 0, t, i, us_b, nb_b, wb_b, y2b, nzb, wgb);
    CP_COMMIT();

    for (int c = 0; c < NCH; c++) {
        int pb = c & 1;
        CP_WAIT0();
        __syncthreads();            // cp.async data visible; prev compute done

        // ---- combine: u += eps*noise, accumulate z0/S2 (thread owns j = t&31)
        #pragma unroll
        for (int ii = 0; ii < 8; ii++) {
            int k = t + ii * 256;
            float v = us[pb * 2048 + k] + EPSN * nb[pb * 2048 + k];
            us[pb * 2048 + k] = v;
            s1 += v;
            s2 += v * v;
        }

        if (c < NCH - 1)
            stage_chunk(c + 1, pb ^ 1, t, i, us_b, nb_b, wb_b, y2b, nzb, wgb);
        CP_COMMIT();
        __syncthreads();            // us[pb] writes visible before compute

        // ---- compute over this thread's n-half ----
        const float*  up = us + pb * 2048 + h * 32 * 32;
        const float2* wp = wb + pb * 1088 + o * WPITCH + h * 32;
        #pragma unroll 4
        for (int nl = 0; nl < 32; nl++) {
            float4 uu = *(const float4*)(up + nl * 32 + j0);
            float2 xv = wp[nl];
            unsigned long long m1 = pk2(xv.x, xv.y);
            unsigned long long m2, m3, m4;
            MUL2(m2, m1, m1);
            MUL2(m3, m2, m1);
            MUL2(m4, m2, m2);
            unsigned long long ua = pk2(uu.x, uu.x);
            unsigned long long ub = pk2(uu.y, uu.y);
            unsigned long long uc = pk2(uu.z, uu.z);
            unsigned long long ud = pk2(uu.w, uu.w);
            FMA2(acc[0],  m1, ua); FMA2(acc[1],  m2, ua);
            FMA2(acc[2],  m3, ua); FMA2(acc[3],  m4, ua);
            FMA2(acc[4],  m1, ub); FMA2(acc[5],  m2, ub);
            FMA2(acc[6],  m3, ub); FMA2(acc[7],  m4, ub);
            FMA2(acc[8],  m1, uc); FMA2(acc[9],  m2, uc);
            FMA2(acc[10], m3, uc); FMA2(acc[11], m4, uc);
            FMA2(acc[12], m1, ud); FMA2(acc[13], m2, ud);
            FMA2(acc[14], m3, ud); FMA2(acc[15], m4, ud);
        }
    }

    // ---- z0 / S2 reduction (thread t built column t&31) ----
    __syncthreads();
    red[t] = s1;
    red[256 + t] = s2;
    __syncthreads();
    if (t < 32) {
        float a = 0.0f, bb = 0.0f;
        #pragma unroll
        for (int w8 = 0; w8 < 8; w8++) {
            a  += red[w8 * 32 + t];
            bb += red[256 + w8 * 32 + t];
        }
        z0s[t] = a;
        s2s[t] = bb;
    }
    __syncthreads();

    // ---- cross-half acc reduction ----
    if (h == 1) {
        #pragma unroll
        for (int k = 0; k < 16; k++) {
            red[r * 32 + 2 * k]     = __uint_as_float((unsigned)acc[k]);
            red[r * 32 + 2 * k + 1] = __uint_as_float((unsigned)(acc[k] >> 32));
        }
    }
    __syncthreads();

    if (h == 0) {
        float wv[4][8];
        #pragma unroll
        for (int loc = 0; loc < 4; loc++)
            #pragma unroll
            for (int pp = 0; pp < 4; pp++) {
                unsigned long long a = acc[loc * 4 + pp];
                int k = loc * 4 + pp;
                wv[loc][2 * pp]     = __uint_as_float((unsigned)a)         + red[r * 32 + 2 * k];
                wv[loc][2 * pp + 1] = __uint_as_float((unsigned)(a >> 32)) + red[r * 32 + 2 * k + 1];
            }

        float w0v[4], wAw[4];
        #pragma unroll
        for (int loc = 0; loc < 4; loc++) {
            w0v[loc] = z0s[j0 + loc];
            wAw[loc] = 0.0f;
        }
        const float* A = g_A + o * 81;
        #pragma unroll
        for (int p = 0; p < 9; p++) {
            float tp[4] = {0.0f, 0.0f, 0.0f, 0.0f};
            #pragma unroll
            for (int q = 0; q < 9; q++) {
                float a = __ldg(&A[p * 9 + q]);
                #pragma unroll
                for (int loc = 0; loc < 4; loc++) {
                    float v = (q == 0) ? w0v[loc] : wv[loc][q - 1];
                    tp[loc] = fmaf(a, v, tp[loc]);
                }
            }
            #pragma unroll
            for (int loc = 0; loc < 4; loc++) {
                float v = (p == 0) ? w0v[loc] : wv[loc][p - 1];
                wAw[loc] = fmaf(tp[loc], v, wAw[loc]);
            }
        }

        float4 res;
        #pragma unroll
        for (int loc = 0; loc < 4; loc++) {
            float S2 = s2s[j0 + loc];
            float z0 = w0v[loc];
            float denom = S2 - z0 * z0 * (1.0f / 576.0f);
            float err = (S2 - wAw[loc]) * (575.0f / 576.0f) / denom;
            ((float*)&res)[loc] = expf(-err);
        }
        *(float4*)(out + ((size_t)(b * 16 + o) * 1024 + i * 32 + j0)) = res;
    }
}

// ---------------------------------------------------------------------------
extern "C" void kernel_launch(void* const* d_in, const int* in_sizes, int n_in,
                              void* d_out, int out_size) {
    const float* y2 = nullptr;
    const float* w  = nullptr;
    const float* nz = nullptr;
    for (int k = 0; k < n_in; k++) {
        if      (in_sizes[k] == 524288)  y2 = (const float*)d_in[k];
        else if (in_sizes[k] == 18432)   w  = (const float*)d_in[k];
        else if (in_sizes[k] == 4718592) nz = (const float*)d_in[k];
    }
    if (!y2 || !w || !nz) {
        y2 = (const float*)d_in[0];
        w  = (const float*)d_in[1];
        nz = (const float*)d_in[2];
    }

    build_A<<<O_, 672>>>(w);

    const int smem_bytes = 16704 * 4;   // 66816 B
    cudaFuncSetAttribute(srn_main, cudaFuncAttributeMaxDynamicSharedMemorySize, smem_bytes);
    srn_main<<<B_ * 32, 256, smem_bytes>>>(y2, w, nz, (float*)d_out);
}